// round 10
// baseline (speedup 1.0000x reference)
#include <cuda_runtime.h>
#include <math.h>

// Shapes (fixed per reference setup_inputs)
#define BB    4
#define NRES  300
#define NCLS  80
#define NKPT  17
#define HMW   64
#define HMHW  4096
#define NWRD  10                     // ceil(300/32)
#define NROWS (BB * NRES * NKPT)     // 20400 heatmap rows
#define NPAD  304                    // greedy loop padded to multiple of 8
#define MROWS (NPAD + 8)             // mask rows incl. prefetch overrun pad

#define IOU_THRF   0.7f
#define SCORE_THRF 0.01f
#define NEGV       (-1000000000.0f)

// Output layout (float32, flattened tuple concat):
// fl [4,300] @0 | fb [4,300,4] @1200 | fs [4,300] @6000 |
// akpts [4,300,17,3] @7200 | vkeep [4,300] @68400
#define OFF_FL 0
#define OFF_FB 1200
#define OFF_FS 6000
#define OFF_AK 7200
#define OFF_VK 68400

// Scratch (device globals — no allocation allowed)
__device__ float    g_maxv[NROWS];
__device__ int      g_midx[NROWS];
__device__ unsigned g_done;
// Cold NMS working arrays (global: keeps kernel smem small for occupancy)
__device__ float    g_sc[BB * NRES];
__device__ int      g_lb[BB * NRES];
__device__ float    g_bx[BB * NRES * 4];
__device__ int      g_order[BB * NRES];
__device__ int      g_keep[BB * NRES];
__device__ int      g_ti[BB * NRES];
__device__ unsigned g_mask[BB * MROWS * NWRD];

__global__ void reset_kernel() { g_done = 0u; }

// ---------------------------------------------------------------------------
// Merged kernel: blocks 0..3 = per-batch NMS + (after spin) finalize;
// blocks 4..20403 = heatmap max/argmax, count completion in g_done.
// Static smem ~10 KB -> heatmap blocks keep 8 blocks/SM under any carveout.
// ---------------------------------------------------------------------------
__global__ __launch_bounds__(256) void main_kernel(
    const float* __restrict__ logits,   // [4,300,80]
    const float* __restrict__ boxes,    // [4,300,4] cxcywh
    const float* __restrict__ sizes,    // [4,2]
    const float* __restrict__ hm,       // [4,300,17,4096]
    const float* __restrict__ koff,     // [4,300,17,2]
    float* __restrict__ out)
{
    const int tid = threadIdx.x;

    // --- NMS shared state (hot, SoA; ~10 KB total) ---
    __shared__ float obx1[NRES], oby1[NRES], obx2[NRES], oby2[NRES];
    __shared__ float sarea[NRES];       // also reused to stash fs? no—dead after masks
    __shared__ float sv[NRES];
    __shared__ int   vv[MROWS];         // valid (sorted) + zero pad for ring
    __shared__ int   selkv[NRES];       // stash: sel | (kv<<15) per output slot
    __shared__ unsigned kw[NWRD];
    __shared__ float red[8];
    __shared__ float sM;
    __shared__ int   sIdx;

    if (blockIdx.x >= BB) {
        // =============== heatmap max/argmax for one (b,n,k) row ===========
        const int row = blockIdx.x - BB;
        const float4* r4 = (const float4*)hm + (size_t)row * (HMHW / 4);

        float4 A  = r4[tid];
        float4 Bv = r4[tid + 256];
        float4 Cv = r4[tid + 512];
        float4 Dv = r4[tid + 768];

        float tm = fmaxf(
            fmaxf(fmaxf(fmaxf(A.x, A.y), fmaxf(A.z, A.w)),
                  fmaxf(fmaxf(Bv.x, Bv.y), fmaxf(Bv.z, Bv.w))),
            fmaxf(fmaxf(fmaxf(Cv.x, Cv.y), fmaxf(Cv.z, Cv.w)),
                  fmaxf(fmaxf(Dv.x, Dv.y), fmaxf(Dv.z, Dv.w))));

        float wm = tm;
        #pragma unroll
        for (int o = 16; o; o >>= 1)
            wm = fmaxf(wm, __shfl_xor_sync(0xffffffffu, wm, o));
        if ((tid & 31) == 0) red[tid >> 5] = wm;
        if (tid == 0) sIdx = 0x7fffffff;
        __syncthreads();
        if (tid == 0) {
            float M = red[0];
            #pragma unroll
            for (int w = 1; w < 8; w++) M = fmaxf(M, red[w]);
            sM = M;
        }
        __syncthreads();
        const float M = sM;

        // only matching thread(s): reload own 16 floats (L1/L2-hot), rescan
        // descending — last write wins = first-occurrence index
        if (tm == M) {
            int gidx = 0;
            #pragma unroll
            for (int q = 3; q >= 0; q--) {
                float4 v = r4[tid + q * 256];
                int base = 4 * (tid + q * 256);
                if (v.w == M) gidx = base + 3;
                if (v.z == M) gidx = base + 2;
                if (v.y == M) gidx = base + 1;
                if (v.x == M) gidx = base;
            }
            atomicMin(&sIdx, gidx);
        }
        __syncthreads();
        if (tid == 0) {
            g_maxv[row] = M;
            g_midx[row] = sIdx;
            __threadfence();
            atomicAdd(&g_done, 1u);     // release: row result published
        }
        return;
    }

    // ======================= NMS for batch b ==============================
    const int b = blockIdx.x;
    const float s0 = sizes[b * 2 + 0];
    const float s1 = sizes[b * 2 + 1];
    float*    sc     = g_sc    + b * NRES;
    int*      lb     = g_lb    + b * NRES;
    float*    bx     = g_bx    + b * NRES * 4;
    int*      order_ = g_order + b * NRES;
    int*      keep   = g_keep  + b * NRES;
    int*      ti     = g_ti    + b * NRES;
    unsigned* mcol   = g_mask  + b * MROWS * NWRD;

    // ---- phase 1: logits argmax + sigmoid + abs box; fused |box| max ----
    float lmax = 0.0f;
    for (int r = tid; r < NRES; r += 256) {
        const float4* lrow = (const float4*)(logits + ((size_t)b * NRES + r) * NCLS);
        float mv = -3.402823466e38f; int mi = 0;
        #pragma unroll 5
        for (int c4 = 0; c4 < NCLS / 4; c4++) {
            float4 v = lrow[c4];
            int cb = c4 * 4;
            if (v.x > mv) { mv = v.x; mi = cb;     }
            if (v.y > mv) { mv = v.y; mi = cb + 1; }
            if (v.z > mv) { mv = v.z; mi = cb + 2; }
            if (v.w > mv) { mv = v.w; mi = cb + 3; }
        }
        float score = 1.0f / (1.0f + expf(-mv));
        sc[r] = score;
        lb[r] = mi;

        const float* brow = boxes + ((size_t)b * NRES + r) * 4;
        float cx = brow[0], cy = brow[1], w = brow[2], h = brow[3];
        float x1 = (cx - w * 0.5f) * s0;
        float y1 = (cy - h * 0.5f) * s1;
        float x2 = (cx + w * 0.5f) * s0;
        float y2 = (cy + h * 0.5f) * s1;
        bx[r * 4 + 0] = x1;
        bx[r * 4 + 1] = y1;
        bx[r * 4 + 2] = x2;
        bx[r * 4 + 3] = y2;
        lmax = fmaxf(lmax, fmaxf(fmaxf(fabsf(x1), fabsf(y1)),
                                 fmaxf(fabsf(x2), fabsf(y2))));
        sv[r] = (score > SCORE_THRF) ? score : NEGV;
    }
    #pragma unroll
    for (int o = 16; o; o >>= 1)
        lmax = fmaxf(lmax, __shfl_xor_sync(0xffffffffu, lmax, o));
    if ((tid & 31) == 0) red[tid >> 5] = lmax;
    __syncthreads();
    if (tid == 0) {
        float v = red[0];
        #pragma unroll
        for (int w = 1; w < 8; w++) v = fmaxf(v, red[w]);
        sM = v + 1.0f;
    }
    __syncthreads();
    const float maxc = sM;

    // ---- phase 2: stable descending rank (stable argsort(-s)) ----
    for (int r = tid; r < NRES; r += 256) {
        float si = sv[r];
        int rk = 0;
        #pragma unroll 4
        for (int j = 0; j < NRES; j++) {
            float sj = sv[j];
            rk += (sj > si) || (sj == si && j < r);
        }
        order_[rk] = r;
    }
    __syncthreads();

    // ---- phase 3: sorted class-offset boxes (SoA) + areas + valid ----
    for (int t = tid; t < NRES; t += 256) {
        int i = order_[t];
        vv[t] = sv[i] != NEGV;
        float off = (float)lb[i] * maxc;
        float x1 = bx[i * 4 + 0] + off;
        float y1 = bx[i * 4 + 1] + off;
        float x2 = bx[i * 4 + 2] + off;
        float y2 = bx[i * 4 + 3] + off;
        obx1[t] = x1; oby1[t] = y1; obx2[t] = x2; oby2[t] = y2;
        sarea[t] = (x2 - x1) * (y2 - y1);
    }
    for (int t = NRES + tid; t < MROWS; t += 256) vv[t] = 0;
    __syncthreads();

    // ---- phase 4: suppression bitmask -> global; pad rows zeroed ----
    for (int task = tid; task < NRES * NWRD; task += 256) {
        int r = task % NRES;
        int w = task / NRES;
        float x1 = obx1[r], y1 = oby1[r], x2 = obx2[r], y2 = oby2[r];
        float ar = sarea[r];
        unsigned m = 0;
        int j0 = w * 32;
        #pragma unroll 8
        for (int jj = 0; jj < 32; jj++) {
            int j = j0 + jj;
            if (j > r && j < NRES) {
                float iw = fmaxf(fminf(x2, obx2[j]) - fmaxf(x1, obx1[j]), 0.0f);
                float ih = fmaxf(fminf(y2, oby2[j]) - fmaxf(y1, oby1[j]), 0.0f);
                float inter = iw * ih;
                float iou = inter / (ar + sarea[j] - inter + 1e-9f);
                if (iou > IOU_THRF) m |= (1u << jj);
            }
        }
        mcol[r * NWRD + w] = m;
    }
    for (int p = tid; p < (MROWS - NRES) * NWRD; p += 256)
        mcol[NRES * NWRD + p] = 0;
    __syncthreads();

    // ---- phase 5: greedy pass (warp 0; lanes 0..9 own words; 8-deep ring) ----
    if (tid < 32) {
        const bool ld = tid < NWRD;
        unsigned buf[8];
        #pragma unroll
        for (int d = 0; d < 8; d++)
            buf[d] = ld ? mcol[d * NWRD + tid] : 0u;
        unsigned sw = 0;
        for (int i0 = 0; i0 < NPAD; i0 += 8) {
            #pragma unroll
            for (int u = 0; u < 8; u++) {
                int i = i0 + u;
                unsigned m = buf[u];
                buf[u] = ld ? mcol[(i + 8) * NWRD + tid] : 0u;   // prefetch
                unsigned word = __shfl_sync(0xffffffffu, sw, i >> 5);
                int is_keep = vv[i] & ~((int)(word >> (i & 31)) & 1);
                if (tid == 0 && i < NRES) keep[i] = is_keep;
                sw |= is_keep ? m : 0u;
            }
        }
    }
    __syncthreads();

    // ---- phase 6: pack keep words ----
    if (tid < NWRD) {
        unsigned m = 0;
        for (int jj = 0; jj < 32; jj++) {
            int i = tid * 32 + jj;
            if (i < NRES && keep[i]) m |= (1u << jj);
        }
        kw[tid] = m;
    }
    __syncthreads();

    // ---- phase 7: ti = kept (sorted order) then suppressed (ascending) ----
    for (int t = tid; t < NRES; t += 256) {
        int wt = t >> 5, bt_ = t & 31;
        int cnt = 0, K = 0;
        #pragma unroll
        for (int w = 0; w < NWRD; w++) {
            int pc = __popc(kw[w]);
            K += pc;
            if (w < wt) cnt += pc;
        }
        cnt += __popc(kw[wt] & ((1u << bt_) - 1u));
        int p = keep[t] ? cnt : (K + t - cnt);
        ti[p] = t;
    }
    __syncthreads();

    // ---- phase 8: box/score/label outputs; stash sel/kv/boxes in smem ----
    // (ob SoA arrays are dead after phase 5 -> reuse them as boxsel stash)
    for (int t = tid; t < NRES; t += 256) {
        int tt  = ti[t];
        int kv  = keep[tt];
        int sel = order_[tt];
        int gi  = b * NRES + t;

        selkv[t] = sel | (kv << 15);

        float b0 = bx[sel * 4 + 0], b1 = bx[sel * 4 + 1];
        float b2 = bx[sel * 4 + 2], b3 = bx[sel * 4 + 3];
        obx1[t] = b0; oby1[t] = b1; obx2[t] = b2; oby2[t] = b3;

        out[OFF_FL + gi] = kv ? (float)lb[sel] : -1.0f;
        float* fb = out + OFF_FB + (size_t)gi * 4;
        fb[0] = kv ? b0 : 0.0f;
        fb[1] = kv ? b1 : 0.0f;
        fb[2] = kv ? b2 : 0.0f;
        fb[3] = kv ? b3 : 0.0f;
        out[OFF_FS + gi] = kv ? sc[sel] : 0.0f;
        out[OFF_VK + gi] = kv ? 1.0f : 0.0f;
    }
    __syncthreads();

    // ---- phase 9: wait for all heatmap rows, then fused finalize ----
    if (tid == 0) {
        while (atomicAdd(&g_done, 0u) < (unsigned)NROWS) __nanosleep(256);
        __threadfence();   // acquire: heatmap results now visible
    }
    __syncthreads();

    for (int q = tid; q < NRES * NKPT; q += 256) {
        int t = q / NKPT;
        int k = q - t * NKPT;
        int sk  = selkv[t];
        int sel = sk & 0x7fff;
        int kv  = sk >> 15;
        int row = (b * NRES + sel) * NKPT + k;

        float mv = g_maxv[row];
        int   bi = g_midx[row];
        float2 ko = *(const float2*)(koff + (size_t)row * 2);

        float nx = fminf(fmaxf(__int2float_rn(bi & (HMW - 1)) / (float)(HMW - 1) + ko.x, 0.0f), 1.0f);
        float ny = fminf(fmaxf(__int2float_rn(bi >> 6)        / (float)(HMW - 1) + ko.y, 0.0f), 1.0f);

        float x1 = obx1[t], y1 = oby1[t], x2 = obx2[t], y2 = oby2[t];
        float ax = x1 + nx * (x2 - x1);
        float ay = y1 + ny * (y2 - y1);

        float* o = out + OFF_AK + ((size_t)(b * NRES + t) * NKPT + k) * 3;
        o[0] = kv ? ax : 0.0f;
        o[1] = kv ? ay : 0.0f;
        o[2] = kv ? mv : 0.0f;
    }
}

// ---------------------------------------------------------------------------
extern "C" void kernel_launch(void* const* d_in, const int* in_sizes, int n_in,
                              void* d_out, int out_size)
{
    const float* logits = (const float*)d_in[0];  // pred_logits
    const float* boxes  = (const float*)d_in[1];  // pred_boxes
    const float* hm     = (const float*)d_in[2];  // pred_keypoint_heatmaps
    const float* koff   = (const float*)d_in[3];  // pred_keypoint_offsets
    const float* sizes  = (const float*)d_in[4];  // orig_target_sizes
    float* out = (float*)d_out;

    reset_kernel<<<1, 1>>>();
    main_kernel<<<BB + NROWS, 256>>>(logits, boxes, sizes, hm, koff, out);
}

// round 11
// speedup vs baseline: 1.2346x; 1.2346x over previous
#include <cuda_runtime.h>
#include <math.h>

// Shapes (fixed per reference setup_inputs)
#define BB    4
#define NRES  300
#define NCLS  80
#define NKPT  17
#define HMW   64
#define HMHW  4096
#define NWRD  10                     // ceil(300/32)
#define NROWS (BB * NRES * NKPT)     // 20400 heatmap rows

#define IOU_THRF   0.7f
#define SCORE_THRF 0.01f
#define NEGV       (-1000000000.0f)

// Output layout (float32, flattened tuple concat):
// fl [4,300] @0 | fb [4,300,4] @1200 | fs [4,300] @6000 |
// akpts [4,300,17,3] @7200 | vkeep [4,300] @68400
#define OFF_FL 0
#define OFF_FB 1200
#define OFF_FS 6000
#define OFF_AK 7200
#define OFF_VK 68400

// Scratch (device globals — no allocation allowed)
__device__ float g_maxv[NROWS];
__device__ int   g_midx[NROWS];
__device__ int   g_selkv[BB * NRES];        // sel | (kv<<15)
__device__ float g_boxsel[BB * NRES * 4];

// ---------------------------------------------------------------------------
// NMS kernel: 4 blocks (one per batch). Standalone & lean; triggers PDL so
// the heatmap kernel launches immediately and overlaps with it.
// ---------------------------------------------------------------------------
__global__ __launch_bounds__(256) void nms_kernel(
    const float* __restrict__ logits,   // [4,300,80]
    const float* __restrict__ boxes,    // [4,300,4] cxcywh
    const float* __restrict__ sizes,    // [4,2]
    float* __restrict__ out)
{
#if __CUDA_ARCH__ >= 900
    cudaTriggerProgrammaticLaunchCompletion();   // all threads: release PDL edge
#endif
    const int tid = threadIdx.x;
    const int b   = blockIdx.x;

    // all NMS scratch in smem (separate kernel -> doesn't tax the stream)
    __shared__ float sc[NRES];
    __shared__ int   lb[NRES];
    __shared__ float bx[NRES * 4];
    __shared__ float sv[NRES];
    __shared__ int   order_[NRES];
    __shared__ float obx1[NRES], oby1[NRES], obx2[NRES], oby2[NRES];
    __shared__ float sarea[NRES];
    __shared__ int   vv[NRES + 1];
    __shared__ unsigned mask[(NRES + 1) * NWRD];
    __shared__ int   keep[NRES];
    __shared__ int   ti[NRES];
    __shared__ unsigned kw[NWRD];
    __shared__ float red[8];
    __shared__ float sM;

    const float s0 = sizes[b * 2 + 0];
    const float s1 = sizes[b * 2 + 1];

    // ---- phase 1: logits argmax + sigmoid + abs box; fused |box| max ----
    float lmax = 0.0f;
    for (int r = tid; r < NRES; r += 256) {
        const float4* lrow = (const float4*)(logits + ((size_t)b * NRES + r) * NCLS);
        float mv = -3.402823466e38f; int mi = 0;
        #pragma unroll 5
        for (int c4 = 0; c4 < NCLS / 4; c4++) {
            float4 v = lrow[c4];
            int cb = c4 * 4;
            if (v.x > mv) { mv = v.x; mi = cb;     }
            if (v.y > mv) { mv = v.y; mi = cb + 1; }
            if (v.z > mv) { mv = v.z; mi = cb + 2; }
            if (v.w > mv) { mv = v.w; mi = cb + 3; }
        }
        float score = 1.0f / (1.0f + expf(-mv));
        sc[r] = score;
        lb[r] = mi;

        const float4 brow = *(const float4*)(boxes + ((size_t)b * NRES + r) * 4);
        float x1 = (brow.x - brow.z * 0.5f) * s0;
        float y1 = (brow.y - brow.w * 0.5f) * s1;
        float x2 = (brow.x + brow.z * 0.5f) * s0;
        float y2 = (brow.y + brow.w * 0.5f) * s1;
        bx[r * 4 + 0] = x1;
        bx[r * 4 + 1] = y1;
        bx[r * 4 + 2] = x2;
        bx[r * 4 + 3] = y2;
        lmax = fmaxf(lmax, fmaxf(fmaxf(fabsf(x1), fabsf(y1)),
                                 fmaxf(fabsf(x2), fabsf(y2))));
        sv[r] = (score > SCORE_THRF) ? score : NEGV;
    }
    #pragma unroll
    for (int o = 16; o; o >>= 1)
        lmax = fmaxf(lmax, __shfl_xor_sync(0xffffffffu, lmax, o));
    if ((tid & 31) == 0) red[tid >> 5] = lmax;
    __syncthreads();
    if (tid == 0) {
        float v = red[0];
        #pragma unroll
        for (int w = 1; w < 8; w++) v = fmaxf(v, red[w]);
        sM = v + 1.0f;
    }
    __syncthreads();
    const float maxc = sM;

    // ---- phase 2: stable descending rank (stable argsort(-s)) ----
    for (int r = tid; r < NRES; r += 256) {
        float si = sv[r];
        int rk = 0;
        #pragma unroll 4
        for (int j = 0; j < NRES; j++) {
            float sj = sv[j];
            rk += (sj > si) || (sj == si && j < r);
        }
        order_[rk] = r;
    }
    __syncthreads();

    // ---- phase 3: sorted class-offset boxes (SoA) + areas + valid ----
    for (int t = tid; t < NRES; t += 256) {
        int i = order_[t];
        vv[t] = sv[i] != NEGV;
        float off = (float)lb[i] * maxc;
        float x1 = bx[i * 4 + 0] + off;
        float y1 = bx[i * 4 + 1] + off;
        float x2 = bx[i * 4 + 2] + off;
        float y2 = bx[i * 4 + 3] + off;
        obx1[t] = x1; oby1[t] = y1; obx2[t] = x2; oby2[t] = y2;
        sarea[t] = (x2 - x1) * (y2 - y1);
    }
    if (tid == 0) vv[NRES] = 0;
    __syncthreads();

    // ---- phase 4: suppression bitmask (SoA, conflict-free lanes) ----
    for (int task = tid; task < NRES * NWRD; task += 256) {
        int r = task % NRES;
        int w = task / NRES;
        float x1 = obx1[r], y1 = oby1[r], x2 = obx2[r], y2 = oby2[r];
        float ar = sarea[r];
        unsigned m = 0;
        int j0 = w * 32;
        #pragma unroll 8
        for (int jj = 0; jj < 32; jj++) {
            int j = j0 + jj;
            if (j > r && j < NRES) {
                float iw = fmaxf(fminf(x2, obx2[j]) - fmaxf(x1, obx1[j]), 0.0f);
                float ih = fmaxf(fminf(y2, oby2[j]) - fmaxf(y1, oby1[j]), 0.0f);
                float inter = iw * ih;
                float iou = inter / (ar + sarea[j] - inter + 1e-9f);
                if (iou > IOU_THRF) m |= (1u << jj);
            }
        }
        mask[r * NWRD + w] = m;
    }
    if (tid < NWRD) mask[NRES * NWRD + tid] = 0;
    __syncthreads();

    // ---- phase 5: greedy pass (warp 0; lanes 0..9 own words; smem masks,
    //      next-iteration operands prefetched off the dependency chain) ----
    if (tid < 32) {
        const bool ld = tid < NWRD;
        unsigned sw = 0;
        unsigned mnext = ld ? mask[tid] : 0u;
        int      vnext = vv[0];
        for (int i = 0; i < NRES; i++) {
            unsigned m = mnext;
            int      v = vnext;
            mnext = ld ? mask[(i + 1) * NWRD + tid] : 0u;  // off-chain
            vnext = vv[i + 1];                             // off-chain
            unsigned word = __shfl_sync(0xffffffffu, sw, i >> 5);
            int is_keep = v & ~((int)(word >> (i & 31)) & 1);
            if (tid == 0) keep[i] = is_keep;
            sw |= is_keep ? m : 0u;
        }
    }
    __syncthreads();

    // ---- phase 6: pack keep words ----
    if (tid < NWRD) {
        unsigned m = 0;
        for (int jj = 0; jj < 32; jj++) {
            int i = tid * 32 + jj;
            if (i < NRES && keep[i]) m |= (1u << jj);
        }
        kw[tid] = m;
    }
    __syncthreads();

    // ---- phase 7: ti = kept (sorted order) then suppressed (ascending) ----
    for (int t = tid; t < NRES; t += 256) {
        int wt = t >> 5, bt_ = t & 31;
        int cnt = 0, K = 0;
        #pragma unroll
        for (int w = 0; w < NWRD; w++) {
            int pc = __popc(kw[w]);
            K += pc;
            if (w < wt) cnt += pc;
        }
        cnt += __popc(kw[wt] & ((1u << bt_) - 1u));
        int p = keep[t] ? cnt : (K + t - cnt);
        ti[p] = t;
    }
    __syncthreads();

    // ---- phase 8: outputs + scratch for finalize ----
    for (int t = tid; t < NRES; t += 256) {
        int tt  = ti[t];
        int kv  = keep[tt];
        int sel = order_[tt];
        int gi  = b * NRES + t;

        g_selkv[gi] = sel | (kv << 15);

        float b0 = bx[sel * 4 + 0], b1 = bx[sel * 4 + 1];
        float b2 = bx[sel * 4 + 2], b3 = bx[sel * 4 + 3];
        g_boxsel[gi * 4 + 0] = b0;
        g_boxsel[gi * 4 + 1] = b1;
        g_boxsel[gi * 4 + 2] = b2;
        g_boxsel[gi * 4 + 3] = b3;

        out[OFF_FL + gi] = kv ? (float)lb[sel] : -1.0f;
        float* fb = out + OFF_FB + (size_t)gi * 4;
        fb[0] = kv ? b0 : 0.0f;
        fb[1] = kv ? b1 : 0.0f;
        fb[2] = kv ? b2 : 0.0f;
        fb[3] = kv ? b3 : 0.0f;
        out[OFF_FS + gi] = kv ? sc[sel] : 0.0f;
        out[OFF_VK + gi] = kv ? 1.0f : 0.0f;
    }
}

// ---------------------------------------------------------------------------
// Heatmap kernel: lean streaming clone (tiny smem, low regs). One block per
// (b,n,k) row; reads the full 334 MB once; no dependency on NMS.
// ---------------------------------------------------------------------------
__global__ __launch_bounds__(256) void hm_kernel(const float* __restrict__ hm)
{
    const int row = blockIdx.x;
    const float4* r4 = (const float4*)hm + (size_t)row * (HMHW / 4);
    const int tid = threadIdx.x;

    __shared__ float red[8];
    __shared__ float sM;
    __shared__ int   sIdx;

    float4 A  = r4[tid];
    float4 Bv = r4[tid + 256];
    float4 Cv = r4[tid + 512];
    float4 Dv = r4[tid + 768];

    float tm = fmaxf(
        fmaxf(fmaxf(fmaxf(A.x, A.y), fmaxf(A.z, A.w)),
              fmaxf(fmaxf(Bv.x, Bv.y), fmaxf(Bv.z, Bv.w))),
        fmaxf(fmaxf(fmaxf(Cv.x, Cv.y), fmaxf(Cv.z, Cv.w)),
              fmaxf(fmaxf(Dv.x, Dv.y), fmaxf(Dv.z, Dv.w))));

    float wm = tm;
    #pragma unroll
    for (int o = 16; o; o >>= 1)
        wm = fmaxf(wm, __shfl_xor_sync(0xffffffffu, wm, o));
    if ((tid & 31) == 0) red[tid >> 5] = wm;
    if (tid == 0) sIdx = 0x7fffffff;
    __syncthreads();
    if (tid == 0) {
        float M = red[0];
        #pragma unroll
        for (int w = 1; w < 8; w++) M = fmaxf(M, red[w]);
        sM = M;
    }
    __syncthreads();
    const float M = sM;

    // matching thread(s): reload own 16 floats (L1-hot), rescan descending —
    // last write wins = first-occurrence index; atomicMin across threads
    if (tm == M) {
        int gidx = 0;
        #pragma unroll
        for (int q = 3; q >= 0; q--) {
            float4 v = r4[tid + q * 256];
            int base = 4 * (tid + q * 256);
            if (v.w == M) gidx = base + 3;
            if (v.z == M) gidx = base + 2;
            if (v.y == M) gidx = base + 1;
            if (v.x == M) gidx = base;
        }
        atomicMin(&sIdx, gidx);
    }
    __syncthreads();
    if (tid == 0) { g_maxv[row] = M; g_midx[row] = sIdx; }
}

// ---------------------------------------------------------------------------
// Finalize: gather (maxv, idx) by sel, compute akpts. One thread per output.
// ---------------------------------------------------------------------------
__global__ __launch_bounds__(128) void finalize_kernel(
    const float* __restrict__ koff,   // [4,300,17,2]
    float* __restrict__ out)
{
    int i = blockIdx.x * 128 + threadIdx.x;   // (b, t, k) flattened
    if (i >= NROWS) return;
    int k  = i % NKPT;
    int gi = i / NKPT;
    int b  = gi / NRES;

    int sk  = g_selkv[gi];
    int sel = sk & 0x7fff;
    int kv  = sk >> 15;
    int row = (b * NRES + sel) * NKPT + k;

    float mv = g_maxv[row];
    int   bi = g_midx[row];
    float2 ko = *(const float2*)(koff + (size_t)row * 2);

    float nx = fminf(fmaxf(__int2float_rn(bi & (HMW - 1)) / (float)(HMW - 1) + ko.x, 0.0f), 1.0f);
    float ny = fminf(fmaxf(__int2float_rn(bi >> 6)        / (float)(HMW - 1) + ko.y, 0.0f), 1.0f);

    float x1 = g_boxsel[gi * 4 + 0], y1 = g_boxsel[gi * 4 + 1];
    float x2 = g_boxsel[gi * 4 + 2], y2 = g_boxsel[gi * 4 + 3];
    float ax = x1 + nx * (x2 - x1);
    float ay = y1 + ny * (y2 - y1);

    float* o = out + OFF_AK + (size_t)i * 3;
    o[0] = kv ? ax : 0.0f;
    o[1] = kv ? ay : 0.0f;
    o[2] = kv ? mv : 0.0f;
}

// ---------------------------------------------------------------------------
extern "C" void kernel_launch(void* const* d_in, const int* in_sizes, int n_in,
                              void* d_out, int out_size)
{
    const float* logits = (const float*)d_in[0];  // pred_logits
    const float* boxes  = (const float*)d_in[1];  // pred_boxes
    const float* hm     = (const float*)d_in[2];  // pred_keypoint_heatmaps
    const float* koff   = (const float*)d_in[3];  // pred_keypoint_offsets
    const float* sizes  = (const float*)d_in[4];  // orig_target_sizes
    float* out = (float*)d_out;

    // 1) NMS first (4 blocks); triggers PDL edge at entry.
    nms_kernel<<<BB, 256>>>(logits, boxes, sizes, out);

    // 2) Heatmap stream with programmatic dependent launch: overlaps NMS.
    //    Deterministic fallback to a plain launch if PDL is unavailable.
    cudaLaunchConfig_t cfg = {};
    cfg.gridDim  = dim3(NROWS);
    cfg.blockDim = dim3(256);
    cfg.stream   = 0;
    cudaLaunchAttribute at[1];
    at[0].id = cudaLaunchAttributeProgrammaticStreamSerialization;
    at[0].val.programmaticStreamSerializationAllowed = 1;
    cfg.attrs = at;
    cfg.numAttrs = 1;
    if (cudaLaunchKernelEx(&cfg, hm_kernel, hm) != cudaSuccess) {
        hm_kernel<<<NROWS, 256>>>(hm);
    }

    // 3) Finalize: stream-ordered after both (PDL preserves downstream order).
    finalize_kernel<<<(NROWS + 127) / 128, 128>>>(koff, out);
}

// round 12
// speedup vs baseline: 2.0777x; 1.6829x over previous
#include <cuda_runtime.h>
#include <math.h>

// Shapes (fixed per reference setup_inputs)
#define BB    4
#define NRES  300
#define NCLS  80
#define NKPT  17
#define HMW   64
#define HMHW  4096
#define NWRD  10                     // ceil(300/32)
#define NROWS (BB * NRES * NKPT)     // 20400 heatmap rows
#define NMS_T 1024                   // NMS block size (32 warps: latency hiding)

#define IOU_THRF   0.7f
#define SCORE_THRF 0.01f
#define NEGV       (-1000000000.0f)

// Output layout (float32, flattened tuple concat):
// fl [4,300] @0 | fb [4,300,4] @1200 | fs [4,300] @6000 |
// akpts [4,300,17,3] @7200 | vkeep [4,300] @68400
#define OFF_FL 0
#define OFF_FB 1200
#define OFF_FS 6000
#define OFF_AK 7200
#define OFF_VK 68400

// Scratch (device globals — no allocation allowed)
__device__ float g_maxv[NROWS];
__device__ int   g_midx[NROWS];
__device__ int   g_selkv[BB * NRES];        // sel | (kv<<15)
__device__ float g_boxsel[BB * NRES * 4];

// ---------------------------------------------------------------------------
// NMS kernel: 4 blocks x 1024 threads (one block per batch). Triggers PDL so
// the heatmap kernel launches immediately and overlaps with it.
// ---------------------------------------------------------------------------
__global__ __launch_bounds__(NMS_T) void nms_kernel(
    const float* __restrict__ logits,   // [4,300,80]
    const float* __restrict__ boxes,    // [4,300,4] cxcywh
    const float* __restrict__ sizes,    // [4,2]
    float* __restrict__ out)
{
#if __CUDA_ARCH__ >= 900
    cudaTriggerProgrammaticLaunchCompletion();   // all threads: release PDL edge
#endif
    const int tid = threadIdx.x;
    const int b   = blockIdx.x;

    __shared__ float sc[NRES];
    __shared__ int   lb[NRES];
    __shared__ float bx[NRES * 4];
    __shared__ float sv[NRES];
    __shared__ int   order_[NRES];
    __shared__ float obx1[NRES], oby1[NRES], obx2[NRES], oby2[NRES];
    __shared__ float sarea[NRES];
    __shared__ int   vv[NRES + 1];
    __shared__ unsigned mask[(NRES + 1) * NWRD];
    __shared__ int   keep[NRES];
    __shared__ int   ti[NRES];
    __shared__ unsigned kw[NWRD];
    __shared__ float red[NMS_T / 32];
    __shared__ float sM;

    const float s0 = sizes[b * 2 + 0];
    const float s1 = sizes[b * 2 + 1];

    // ---- phase 1: logits argmax + sigmoid + abs box; fused |box| max ----
    float lmax = 0.0f;
    if (tid < NRES) {
        const int r = tid;
        const float4* lrow = (const float4*)(logits + ((size_t)b * NRES + r) * NCLS);
        float mv = -3.402823466e38f; int mi = 0;
        #pragma unroll 5
        for (int c4 = 0; c4 < NCLS / 4; c4++) {
            float4 v = lrow[c4];
            int cb = c4 * 4;
            if (v.x > mv) { mv = v.x; mi = cb;     }
            if (v.y > mv) { mv = v.y; mi = cb + 1; }
            if (v.z > mv) { mv = v.z; mi = cb + 2; }
            if (v.w > mv) { mv = v.w; mi = cb + 3; }
        }
        float score = 1.0f / (1.0f + expf(-mv));
        sc[r] = score;
        lb[r] = mi;

        const float4 brow = *(const float4*)(boxes + ((size_t)b * NRES + r) * 4);
        float x1 = (brow.x - brow.z * 0.5f) * s0;
        float y1 = (brow.y - brow.w * 0.5f) * s1;
        float x2 = (brow.x + brow.z * 0.5f) * s0;
        float y2 = (brow.y + brow.w * 0.5f) * s1;
        bx[r * 4 + 0] = x1;
        bx[r * 4 + 1] = y1;
        bx[r * 4 + 2] = x2;
        bx[r * 4 + 3] = y2;
        lmax = fmaxf(fmaxf(fabsf(x1), fabsf(y1)), fmaxf(fabsf(x2), fabsf(y2)));
        sv[r] = (score > SCORE_THRF) ? score : NEGV;
    }
    #pragma unroll
    for (int o = 16; o; o >>= 1)
        lmax = fmaxf(lmax, __shfl_xor_sync(0xffffffffu, lmax, o));
    if ((tid & 31) == 0) red[tid >> 5] = lmax;
    __syncthreads();
    if (tid < 32) {
        float v = red[tid];
        #pragma unroll
        for (int o = 16; o; o >>= 1)
            v = fmaxf(v, __shfl_xor_sync(0xffffffffu, v, o));
        if (tid == 0) sM = v + 1.0f;
    }
    __syncthreads();
    const float maxc = sM;

    // ---- phase 2: stable descending rank (stable argsort(-s)) ----
    if (tid < NRES) {
        const int r = tid;
        float si = sv[r];
        int rk = 0;
        #pragma unroll 4
        for (int j = 0; j < NRES; j++) {
            float sj = sv[j];
            rk += (sj > si) || (sj == si && j < r);
        }
        order_[rk] = r;
    }
    __syncthreads();

    // ---- phase 3: sorted class-offset boxes (SoA) + areas + valid ----
    if (tid < NRES) {
        const int t = tid;
        int i = order_[t];
        vv[t] = sv[i] != NEGV;
        float off = (float)lb[i] * maxc;
        float x1 = bx[i * 4 + 0] + off;
        float y1 = bx[i * 4 + 1] + off;
        float x2 = bx[i * 4 + 2] + off;
        float y2 = bx[i * 4 + 3] + off;
        obx1[t] = x1; oby1[t] = y1; obx2[t] = x2; oby2[t] = y2;
        sarea[t] = (x2 - x1) * (y2 - y1);
    }
    if (tid == 0) vv[NRES] = 0;
    __syncthreads();

    // ---- phase 4: suppression bitmask (3000 tasks over 1024 threads) ----
    // task -> (r = task % NRES, w = task / NRES): lanes get consecutive r
    // (conflict-free per-r loads) and uniform w (broadcast per-j loads).
    for (int task = tid; task < NRES * NWRD; task += NMS_T) {
        int r = task % NRES;
        int w = task / NRES;
        float x1 = obx1[r], y1 = oby1[r], x2 = obx2[r], y2 = oby2[r];
        float ar = sarea[r];
        unsigned m = 0;
        int j0 = w * 32;
        #pragma unroll 8
        for (int jj = 0; jj < 32; jj++) {
            int j = j0 + jj;
            if (j > r && j < NRES) {
                float iw = fmaxf(fminf(x2, obx2[j]) - fmaxf(x1, obx1[j]), 0.0f);
                float ih = fmaxf(fminf(y2, oby2[j]) - fmaxf(y1, oby1[j]), 0.0f);
                float inter = iw * ih;
                float iou = inter / (ar + sarea[j] - inter + 1e-9f);
                if (iou > IOU_THRF) m |= (1u << jj);
            }
        }
        mask[r * NWRD + w] = m;
    }
    if (tid < NWRD) mask[NRES * NWRD + tid] = 0;
    __syncthreads();

    // ---- phase 5: greedy pass (warp 0; lanes 0..9 own suppression words;
    //      next-iteration operands prefetched off the dependency chain) ----
    if (tid < 32) {
        const bool ld = tid < NWRD;
        unsigned sw = 0;
        unsigned mnext = ld ? mask[tid] : 0u;
        int      vnext = vv[0];
        for (int i = 0; i < NRES; i++) {
            unsigned m = mnext;
            int      v = vnext;
            mnext = ld ? mask[(i + 1) * NWRD + tid] : 0u;  // off-chain
            vnext = vv[i + 1];                             // off-chain
            unsigned word = __shfl_sync(0xffffffffu, sw, i >> 5);
            int is_keep = v & ~((int)(word >> (i & 31)) & 1);
            if (tid == 0) keep[i] = is_keep;
            sw |= is_keep ? m : 0u;
        }
    }
    __syncthreads();

    // ---- phase 6: pack keep words ----
    if (tid < NWRD) {
        unsigned m = 0;
        for (int jj = 0; jj < 32; jj++) {
            int i = tid * 32 + jj;
            if (i < NRES && keep[i]) m |= (1u << jj);
        }
        kw[tid] = m;
    }
    __syncthreads();

    // ---- phase 7: ti = kept (sorted order) then suppressed (ascending) ----
    if (tid < NRES) {
        const int t = tid;
        int wt = t >> 5, bt_ = t & 31;
        int cnt = 0, K = 0;
        #pragma unroll
        for (int w = 0; w < NWRD; w++) {
            int pc = __popc(kw[w]);
            K += pc;
            if (w < wt) cnt += pc;
        }
        cnt += __popc(kw[wt] & ((1u << bt_) - 1u));
        int p = keep[t] ? cnt : (K + t - cnt);
        ti[p] = t;
    }
    __syncthreads();

    // ---- phase 8: outputs + scratch for finalize ----
    if (tid < NRES) {
        const int t = tid;
        int tt  = ti[t];
        int kv  = keep[tt];
        int sel = order_[tt];
        int gi  = b * NRES + t;

        g_selkv[gi] = sel | (kv << 15);

        float b0 = bx[sel * 4 + 0], b1 = bx[sel * 4 + 1];
        float b2 = bx[sel * 4 + 2], b3 = bx[sel * 4 + 3];
        g_boxsel[gi * 4 + 0] = b0;
        g_boxsel[gi * 4 + 1] = b1;
        g_boxsel[gi * 4 + 2] = b2;
        g_boxsel[gi * 4 + 3] = b3;

        out[OFF_FL + gi] = kv ? (float)lb[sel] : -1.0f;
        float* fb = out + OFF_FB + (size_t)gi * 4;
        fb[0] = kv ? b0 : 0.0f;
        fb[1] = kv ? b1 : 0.0f;
        fb[2] = kv ? b2 : 0.0f;
        fb[3] = kv ? b3 : 0.0f;
        out[OFF_FS + gi] = kv ? sc[sel] : 0.0f;
        out[OFF_VK + gi] = kv ? 1.0f : 0.0f;
    }
}

// ---------------------------------------------------------------------------
// Heatmap kernel: lean streaming kernel (tiny smem, low regs). One block per
// (b,n,k) row; reads the full 334 MB once; no dependency on NMS.
// ---------------------------------------------------------------------------
__global__ __launch_bounds__(256) void hm_kernel(const float* __restrict__ hm)
{
    const int row = blockIdx.x;
    const float4* r4 = (const float4*)hm + (size_t)row * (HMHW / 4);
    const int tid = threadIdx.x;

    __shared__ float red[8];
    __shared__ float sM;
    __shared__ int   sIdx;

    float4 A  = r4[tid];
    float4 Bv = r4[tid + 256];
    float4 Cv = r4[tid + 512];
    float4 Dv = r4[tid + 768];

    float tm = fmaxf(
        fmaxf(fmaxf(fmaxf(A.x, A.y), fmaxf(A.z, A.w)),
              fmaxf(fmaxf(Bv.x, Bv.y), fmaxf(Bv.z, Bv.w))),
        fmaxf(fmaxf(fmaxf(Cv.x, Cv.y), fmaxf(Cv.z, Cv.w)),
              fmaxf(fmaxf(Dv.x, Dv.y), fmaxf(Dv.z, Dv.w))));

    float wm = tm;
    #pragma unroll
    for (int o = 16; o; o >>= 1)
        wm = fmaxf(wm, __shfl_xor_sync(0xffffffffu, wm, o));
    if ((tid & 31) == 0) red[tid >> 5] = wm;
    if (tid == 0) sIdx = 0x7fffffff;
    __syncthreads();
    if (tid == 0) {
        float M = red[0];
        #pragma unroll
        for (int w = 1; w < 8; w++) M = fmaxf(M, red[w]);
        sM = M;
    }
    __syncthreads();
    const float M = sM;

    // matching thread(s): reload own 16 floats (L1-hot), rescan descending —
    // last write wins = first-occurrence index; atomicMin across threads
    if (tm == M) {
        int gidx = 0;
        #pragma unroll
        for (int q = 3; q >= 0; q--) {
            float4 v = r4[tid + q * 256];
            int base = 4 * (tid + q * 256);
            if (v.w == M) gidx = base + 3;
            if (v.z == M) gidx = base + 2;
            if (v.y == M) gidx = base + 1;
            if (v.x == M) gidx = base;
        }
        atomicMin(&sIdx, gidx);
    }
    __syncthreads();
    if (tid == 0) { g_maxv[row] = M; g_midx[row] = sIdx; }
}

// ---------------------------------------------------------------------------
// Finalize: gather (maxv, idx) by sel, compute akpts. One thread per output.
// ---------------------------------------------------------------------------
__global__ __launch_bounds__(128) void finalize_kernel(
    const float* __restrict__ koff,   // [4,300,17,2]
    float* __restrict__ out)
{
    int i = blockIdx.x * 128 + threadIdx.x;   // (b, t, k) flattened
    if (i >= NROWS) return;
    int k  = i % NKPT;
    int gi = i / NKPT;
    int b  = gi / NRES;

    int sk  = g_selkv[gi];
    int sel = sk & 0x7fff;
    int kv  = sk >> 15;
    int row = (b * NRES + sel) * NKPT + k;

    float mv = g_maxv[row];
    int   bi = g_midx[row];
    float2 ko = *(const float2*)(koff + (size_t)row * 2);

    float nx = fminf(fmaxf(__int2float_rn(bi & (HMW - 1)) / (float)(HMW - 1) + ko.x, 0.0f), 1.0f);
    float ny = fminf(fmaxf(__int2float_rn(bi >> 6)        / (float)(HMW - 1) + ko.y, 0.0f), 1.0f);

    float x1 = g_boxsel[gi * 4 + 0], y1 = g_boxsel[gi * 4 + 1];
    float x2 = g_boxsel[gi * 4 + 2], y2 = g_boxsel[gi * 4 + 3];
    float ax = x1 + nx * (x2 - x1);
    float ay = y1 + ny * (y2 - y1);

    float* o = out + OFF_AK + (size_t)i * 3;
    o[0] = kv ? ax : 0.0f;
    o[1] = kv ? ay : 0.0f;
    o[2] = kv ? mv : 0.0f;
}

// ---------------------------------------------------------------------------
extern "C" void kernel_launch(void* const* d_in, const int* in_sizes, int n_in,
                              void* d_out, int out_size)
{
    const float* logits = (const float*)d_in[0];  // pred_logits
    const float* boxes  = (const float*)d_in[1];  // pred_boxes
    const float* hm     = (const float*)d_in[2];  // pred_keypoint_heatmaps
    const float* koff   = (const float*)d_in[3];  // pred_keypoint_offsets
    const float* sizes  = (const float*)d_in[4];  // orig_target_sizes
    float* out = (float*)d_out;

    // 1) NMS first (4 blocks x 1024 threads); triggers PDL edge at entry.
    nms_kernel<<<BB, NMS_T>>>(logits, boxes, sizes, out);

    // 2) Heatmap stream with programmatic dependent launch: overlaps NMS.
    //    Deterministic fallback to a plain launch if PDL is unavailable.
    cudaLaunchConfig_t cfg = {};
    cfg.gridDim  = dim3(NROWS);
    cfg.blockDim = dim3(256);
    cfg.stream   = 0;
    cudaLaunchAttribute at[1];
    at[0].id = cudaLaunchAttributeProgrammaticStreamSerialization;
    at[0].val.programmaticStreamSerializationAllowed = 1;
    cfg.attrs = at;
    cfg.numAttrs = 1;
    if (cudaLaunchKernelEx(&cfg, hm_kernel, hm) != cudaSuccess) {
        hm_kernel<<<NROWS, 256>>>(hm);
    }

    // 3) Finalize: stream-ordered after both (PDL preserves downstream order).
    finalize_kernel<<<(NROWS + 127) / 128, 128>>>(koff, out);
}